// round 8
// baseline (speedup 1.0000x reference)
#include <cuda_runtime.h>
#include <math.h>

// ---------------- problem constants ----------------
#define BB   8
#define CC   684
#define HHD  16
#define WWD  64
#define PP   1024
#define TT   32
#define HID  256
#define ATT  512
#define COVD 512
#define VOC  111
#define LOCD 432
#define KC   11
#define RAT  16
#define NB   128

// ---------------- scratch ----------------
__device__ float d_mask[BB*PP];
__device__ float d_msum[BB];
__device__ float d_avg[BB*CC];
__device__ float d_hid[2][BB*HID];
__device__ float d_locw[BB*HID];
__device__ float d_kcovT[KC*KC*COVD];
__device__ float d_KfT[KC*KC*ATT];
__device__ float d_cnnT[(size_t)BB*PP*CC];
__device__ float d_ctrans[(size_t)BB*PP*ATT];
__device__ float d_cnnW[(size_t)BB*PP*HID];
__device__ float d_embseq[TT*BB*HID];
__device__ float d_giall[TT*BB*3*HID];
__device__ float d_embwall[TT*BB*HID];
__device__ float d_query[BB*ATT];
__device__ float d_asum[BB*PP];
__device__ float d_energy[BB*PP];
__device__ float d_WhhT[HID*3*HID];
__device__ float d_WhqT[HID*ATT];
__device__ float d_WstT[HID*HID];
__device__ float d_WoutT[HID*VOC];
__device__ unsigned d_bcnt[BB*32];   // padded 128B apart

// ---------------- helpers ----------------
__device__ __forceinline__ float warp_red(float s){
#pragma unroll
    for(int o=16;o;o>>=1) s += __shfl_down_sync(0xffffffffu, s, o);
    return s;
}
__device__ __forceinline__ unsigned long long pack2(float lo, float hi){
    unsigned long long r;
    asm("mov.b64 %0, {%1,%2};" : "=l"(r) : "f"(lo), "f"(hi));
    return r;
}
__device__ __forceinline__ void fma2(unsigned long long &d, unsigned long long a, unsigned long long b){
    asm("fma.rn.f32x2 %0, %1, %2, %0;" : "+l"(d) : "l"(a), "l"(b));
}
__device__ __forceinline__ float2 unpack2(unsigned long long v){
    float2 f;
    asm("mov.b64 {%0,%1}, %2;" : "=f"(f.x), "=f"(f.y) : "l"(v));
    return f;
}
__device__ __forceinline__ float tanha(float x){
    asm("tanh.approx.f32 %0, %0;" : "+f"(x));
    return x;
}

// =================== Launch 0: k_preA ===================
#define PA_INIT  0
#define PA_CNNT  8
#define PA_KCOV  (PA_CNNT+5632)
#define PA_EMB   (PA_KCOV+242)
#define PA_WHH   (PA_EMB+256)
#define PA_WHQ   (PA_WHH+768)
#define PA_WST   (PA_WHQ+512)
#define PA_WOUT  (PA_WST+256)
#define PA_TOT   (PA_WOUT+112)

__global__ void __launch_bounds__(256) k_preA(
    const float* __restrict__ imask, const float* __restrict__ K_cov,
    const int*   __restrict__ labels,const float* __restrict__ emb,
    const float* __restrict__ W_hh,  const float* __restrict__ W_hq,
    const float* __restrict__ W_state,const float* __restrict__ W_out,
    const float* __restrict__ cnn)
{
    const int blk = blockIdx.x, tid = threadIdx.x;
    __shared__ float red[256];
    __shared__ float tile[32][33];

    if(blk < PA_CNNT){
        int b = blk;
        float s = 0.f;
        for(int i=tid;i<PP;i+=256){
            int hh = i>>6, ww = i&63;
            float m = imask[(size_t)b*(256*1024) + (size_t)(hh*RAT)*1024 + ww*RAT];
            d_mask[b*PP+i] = m;
            d_asum[b*PP+i] = 0.f;
            s += m;
        }
        red[tid]=s; __syncthreads();
        for(int o=128;o;o>>=1){ if(tid<o) red[tid]+=red[tid+o]; __syncthreads(); }
        if(tid==0){ d_msum[b]=red[0]; d_bcnt[b*32]=0u; }
    } else if(blk < PA_KCOV){
        int idx = blk - PA_CNNT;
        int bb = idx / 704, rem = idx % 704;
        int c0 = (rem>>5)*32, p0 = (rem&31)*32;
        int tx = tid&31, ty = tid>>5;
#pragma unroll
        for(int pass=0;pass<4;pass++){
            int r = pass*8+ty;
            if(c0+r < CC) tile[r][tx] = cnn[((size_t)(bb*CC + c0+r))*PP + p0+tx];
        }
        __syncthreads();
#pragma unroll
        for(int pass=0;pass<4;pass++){
            int r = pass*8+ty;
            if(c0+tx < CC) d_cnnT[((size_t)(bb*PP + p0+r))*CC + c0+tx] = tile[tx][r];
        }
    } else if(blk < PA_EMB){
        int e = (blk-PA_KCOV)*256 + tid;
        if(e < COVD*KC*KC){
            int c = e/(KC*KC), ij = e - c*(KC*KC);
            d_kcovT[ij*COVD + c] = K_cov[e];
        }
    } else if(blk < PA_WHH){
        int e = (blk-PA_EMB)*256 + tid;
        int k = e & (HID-1);
        int tb = e >> 8;
        int b = tb & 7, t = tb >> 3;
        int lbl = (t==0) ? 1 : labels[b*TT + (t-1)];
        d_embseq[e] = emb[(size_t)lbl*HID + k];
    } else if(blk < PA_WHQ){
        int e = (blk-PA_WHH)*256 + tid;
        int c = e/768, r = e - c*768;
        d_WhhT[e] = W_hh[(size_t)r*HID + c];
    } else if(blk < PA_WST){
        int e = (blk-PA_WHQ)*256 + tid;
        int c = e/ATT, q = e - c*ATT;
        d_WhqT[e] = W_hq[(size_t)q*HID + c];
    } else if(blk < PA_WOUT){
        int e = (blk-PA_WST)*256 + tid;
        int c = e/HID, j = e - c*HID;
        d_WstT[e] = W_state[(size_t)j*HID + c];
    } else {
        int e = (blk-PA_WOUT)*256 + tid;
        if(e < HID*VOC){
            int c = e/VOC, v = e - c*VOC;
            d_WoutT[e] = W_out[(size_t)v*HID + c];
        }
    }
}

// =================== Launch 1: k_preB ===================
#define PB_CT  0
#define PB_CW  1024
#define PB_GI  1536
#define PB_EW  1584
#define PB_KF  1600
#define PB_AVG 1616
#define PB_TOT 2300

__device__ void gemm64(const float* __restrict__ A, int M, int K,
                       const float* __restrict__ Wt, const float* __restrict__ bias,
                       float* __restrict__ out, int N, int ptile, int ntile,
                       float2 (*As)[68], float (*Bs)[68])
{
    int pt = ptile*64, at = ntile*64;
    int tid = threadIdx.x;
    int tx = tid & 15, ty = tid >> 4;
    unsigned long long acc2[4][2];
#pragma unroll
    for(int i=0;i<4;i++){ acc2[i][0]=0ull; acc2[i][1]=0ull; }

    for(int c0=0;c0<K;c0+=16){
#pragma unroll
        for(int l=0;l<4;l++){
            int lin = tid + l*256;
            int k = lin & 15, r = lin >> 4;
            int c = c0 + k;
            float av = (c < K && pt+r < M) ? A[((size_t)(pt+r))*K + c] : 0.f;
            As[k][r] = make_float2(av, av);
            Bs[k][r] = (c < K) ? Wt[((size_t)(at+r))*K + c] : 0.f;
        }
        __syncthreads();
#pragma unroll
        for(int k=0;k<16;k++){
            unsigned long long ra2[4], rb2[2];
#pragma unroll
            for(int i=0;i<4;i++) ra2[i] = *(const unsigned long long*)&As[k][ty*4+i];
            rb2[0] = *(const unsigned long long*)&Bs[k][tx*4];
            rb2[1] = *(const unsigned long long*)&Bs[k][tx*4+2];
#pragma unroll
            for(int i=0;i<4;i++){
                fma2(acc2[i][0], ra2[i], rb2[0]);
                fma2(acc2[i][1], ra2[i], rb2[1]);
            }
        }
        __syncthreads();
    }
#pragma unroll
    for(int i=0;i<4;i++){
        int p = pt + ty*4 + i;
        if(p < M){
#pragma unroll
            for(int jp=0;jp<2;jp++){
                int aa = at + tx*4 + jp*2;
                float2 v = unpack2(acc2[i][jp]);
                float b0 = bias ? bias[aa]   : 0.f;
                float b1 = bias ? bias[aa+1] : 0.f;
                out[(size_t)p*N + aa]   = v.x + b0;
                out[(size_t)p*N + aa+1] = v.y + b1;
            }
        }
    }
}

__global__ void __launch_bounds__(256) k_preB(
    const float* __restrict__ cnn,
    const float* __restrict__ K_enc, const float* __restrict__ b_enc,
    const float* __restrict__ W_ctx,
    const float* __restrict__ W_ih,  const float* __restrict__ b_ih,
    const float* __restrict__ W_embw,const float* __restrict__ b_embw,
    const float* __restrict__ W_att)
{
    __shared__ float2 As[16][68];
    __shared__ float  Bs[16][68];
    const int blk = blockIdx.x;

    if(blk < PB_CW){
        int i = blk;
        gemm64(d_cnnT, BB*PP, CC, K_enc, b_enc, d_ctrans, ATT, i & 127, i >> 7, As, Bs);
    } else if(blk < PB_GI){
        int i = blk - PB_CW;
        gemm64(d_cnnT, BB*PP, CC, W_ctx, (const float*)0, d_cnnW, HID, i & 127, i >> 7, As, Bs);
    } else if(blk < PB_EW){
        int i = blk - PB_GI;
        gemm64(d_embseq, TT*BB, HID, W_ih, b_ih, d_giall, 3*HID, i & 3, i >> 2, As, Bs);
    } else if(blk < PB_KF){
        int i = blk - PB_EW;
        gemm64(d_embseq, TT*BB, HID, W_embw, b_embw, d_embwall, HID, i & 3, i >> 2, As, Bs);
    } else if(blk < PB_AVG){
        int i = blk - PB_KF;
        gemm64(d_kcovT, KC*KC, COVD, W_att, (const float*)0, d_KfT, ATT, i & 1, i >> 1, As, Bs);
    } else {
        int gw = (blk - PB_AVG)*8 + (threadIdx.x >> 5);
        int lane = threadIdx.x & 31;
        if(gw < BB*CC){
            int b = gw / CC;
            const float* x = cnn + (size_t)gw*PP;
            const float* m = d_mask + b*PP;
            float s = 0.f;
            for(int p=lane;p<PP;p+=32) s += x[p]*m[p];
            s = warp_red(s);
            if(lane==0) d_avg[gw] = s / d_msum[b];
        }
    }
}

// =================== Launch 2: k_preC ===================
__global__ void __launch_bounds__(256) k_preC(
    const float* __restrict__ W_init, const float* __restrict__ b_init,
    const float* __restrict__ W_loc,  const float* __restrict__ b_loc,
    const float* __restrict__ locp)
{
    int gw = blockIdx.x*8 + (threadIdx.x >> 5);
    int lane = threadIdx.x & 31;
    if(gw < BB*HID){
        int b = gw / HID, j = gw - b*HID;
        const float* wv = W_init + (size_t)j*CC;
        const float* av = d_avg + b*CC;
        float s = 0.f;
        for(int c=lane;c<CC;c+=32) s += wv[c]*av[c];
        s = warp_red(s);
        if(lane==0) d_hid[0][gw] = tanhf(s + b_init[j]);
    } else if(gw < 2*BB*HID){
        int g2 = gw - BB*HID;
        int b = g2 / HID, j = g2 - b*HID;
        const float* wv = W_loc + (size_t)j*LOCD;
        const float* xv = locp + (size_t)b*LOCD;
        float s = 0.f;
        for(int c=lane;c<LOCD;c+=32) s += wv[c]*xv[c];
        s = warp_red(s);
        if(lane==0) d_locw[g2] = s + b_loc[j];
    }
}

// =================== Launch 3: k_loop (persistent) ===================
__global__ void __launch_bounds__(512,1) k_loop(
    const float* __restrict__ Wac,   const float* __restrict__ bac,
    const float* __restrict__ bhh,   const float* __restrict__ bhq,
    const float* __restrict__ bstate,const float* __restrict__ bctx,
    const float* __restrict__ bout,
    float* __restrict__ out_probs,   float* __restrict__ out_alphas)
{
    const int bid = blockIdx.x;
    const int h   = bid >> 3;         // 0..15
    const int b   = bid & 7;
    const int tid = threadIdx.x;
    const int lane = tid & 31, wid = tid >> 5;
    unsigned bt = 0;

    __shared__ float2 taps2[KC*74];
    __shared__ float  spart[4][4][16];
    __shared__ float  wred[33];
    __shared__ int    wcnt[16];
    __shared__ int    pl[64];
    __shared__ float  wl[64];
    __shared__ int    nact_s;
    __shared__ float  hg[HID];
    __shared__ float  hp[2][3][HID];   // hnew partials [half][gate][j]
    __shared__ float  hn_s[HID];
    __shared__ float  qred[8][64];
    __shared__ float  sacc[2][HID];
    __shared__ float  st_s[HID];
    __shared__ float  os[HID];
    __shared__ float  pp4[4][128];

    auto bar = [&](){
        __syncthreads();
        bt += 16;
        if(tid==0){
            __threadfence();
            atomicAdd(&d_bcnt[b*32], 1u);
            while(*(volatile unsigned*)&d_bcnt[b*32] < bt) __nanosleep(16);
            __threadfence();
        }
        __syncthreads();
    };

    // ---- redundant GRU hnew (full 256 outputs in this block) for step s ----
    // reads d_hid[s&1], leaves result in hn_s; h==1 also writes d_hid[(s+1)&1]
    auto gru_full = [&](int s){
        if(tid < HID) hg[tid] = d_hid[s&1][b*HID + tid];
        __syncthreads();
        {
            int j = tid & 255, half = tid >> 8;
            float pr=0.f, pz=0.f, pn=0.f;
#pragma unroll 4
            for(int c=half*128; c<half*128+128; c++){
                float hc = hg[c];
                const float* w = d_WhhT + c*3*HID;
                pr = fmaf(w[j],        hc, pr);
                pz = fmaf(w[HID+j],    hc, pz);
                pn = fmaf(w[2*HID+j],  hc, pn);
            }
            hp[half][0][j]=pr; hp[half][1][j]=pz; hp[half][2][j]=pn;
        }
        __syncthreads();
        if(tid < HID){
            int j = tid;
            float hr = bhh[j]       + hp[0][0][j] + hp[1][0][j];
            float hz = bhh[HID+j]   + hp[0][1][j] + hp[1][1][j];
            float hv = bhh[2*HID+j] + hp[0][2][j] + hp[1][2][j];
            const float* gi = d_giall + (size_t)(s*BB+b)*3*HID;
            float r = 1.f/(1.f+expf(-(gi[j]+hr)));
            float z = 1.f/(1.f+expf(-(gi[HID+j]+hz)));
            float n = tanhf(gi[2*HID+j] + r*hv);
            float hnew = (1.f - z)*n + z*hg[j];
            hn_s[j] = hnew;
            if(h == 1) d_hid[(s+1)&1][b*HID + j] = hnew;
        }
        __syncthreads();
    };

    // ---- query chunk for step s (uses hn_s): blocks h=1..8, q in [64(h-1),64h) ----
    auto query_q = [&](int s){
        int q0 = (h-1)*64;
        {
            int qq = tid & 63, cp = tid >> 6;
            int q = q0 + qq;
            float p = 0.f;
#pragma unroll 4
            for(int c=cp*32; c<cp*32+32; c++)
                p = fmaf(d_WhqT[c*ATT + q], hn_s[c], p);
            qred[cp][qq] = p;
        }
        __syncthreads();
        if(tid < 64){
            int q = q0 + tid;
            float s2 = bhq[q];
#pragma unroll
            for(int cp=0;cp<8;cp++) s2 += qred[cp][tid];
            d_query[b*ATT + q] = s2;
        }
        __syncthreads();
    };

    // -------- bootstrap: hnew(0)+query(0) on blocks h=1..8 --------
    if(h>=1 && h<=8){ gru_full(0); query_q(0); }
    bar();

    for(int t=0; t<TT; t++){
        // =========== Phase E: energy ===========
        {
            const int ag = tid & 127, wg = tid >> 7;
            const int a0 = ag << 2,  w0 = wg << 4;
            unsigned long long acc01[16], acc23[16];
#pragma unroll
            for(int w=0;w<16;w++){ acc01[w]=0ull; acc23[w]=0ull; }

            if(t > 0){
                for(int idx=tid; idx<KC*74; idx+=512){
                    int i = idx/74, w2 = idx - i*74;
                    int hh = h + i - 5, wgl = w2 - 5;
                    float v = 0.f;
                    if(hh>=0 && hh<HHD && wgl>=0 && wgl<WWD) v = d_asum[b*PP + hh*WWD + wgl];
                    taps2[idx] = make_float2(v, v);
                }
                __syncthreads();
#pragma unroll 1
                for(int i=0;i<KC;i++){
#pragma unroll
                    for(int half=0;half<2;half++){
                        unsigned long long th[18];
                        const unsigned long long* trow =
                            (const unsigned long long*)(&taps2[i*74 + w0 + half*8]);
#pragma unroll
                        for(int x=0;x<18;x++) th[x] = trow[x];
#pragma unroll
                        for(int j=0;j<KC;j++){
                            float4 kv = *(const float4*)(d_KfT + (i*KC+j)*ATT + a0);
                            unsigned long long k01 = pack2(kv.x, kv.y);
                            unsigned long long k23 = pack2(kv.z, kv.w);
#pragma unroll
                            for(int w=0;w<8;w++){
                                fma2(acc01[half*8+w], k01, th[j+w]);
                                fma2(acc23[half*8+w], k23, th[j+w]);
                            }
                        }
                    }
                }
                __syncthreads();
            }

            float4 q4  = *(const float4*)(d_query + b*ATT + a0);
            float4 wa4 = *(const float4*)(Wac + a0);
            const float* ctbase = d_ctrans + ((size_t)(b*PP + h*WWD + w0))*ATT + a0;
            int wiw = (tid >> 5) & 3;
#pragma unroll
            for(int w=0;w<16;w++){
                float4 ct = *(const float4*)(ctbase + (size_t)w*ATT);
                float2 a01 = unpack2(acc01[w]);
                float2 a23 = unpack2(acc23[w]);
                float v = wa4.x * tanha(q4.x + a01.x + ct.x)
                        + wa4.y * tanha(q4.y + a01.y + ct.y)
                        + wa4.z * tanha(q4.z + a23.x + ct.z)
                        + wa4.w * tanha(q4.w + a23.y + ct.w);
#pragma unroll
                for(int o=16;o;o>>=1) v += __shfl_down_sync(0xffffffffu, v, o);
                if(lane==0) spart[wg][wiw][w] = v;
            }
            __syncthreads();
            if(tid < 64){
                int wgo = tid >> 4, wlx = tid & 15;
                float e = spart[wgo][0][wlx] + spart[wgo][1][wlx]
                        + spart[wgo][2][wlx] + spart[wgo][3][wlx];
                d_energy[b*PP + h*WWD + tid] = e + bac[0];
            }
        }
        bar();

        // =========== Phase B ===========
        if(h == 0){
            // ---- softmax (step t) ----
            int p0 = tid, p1 = tid + 512;
            float e0 = d_energy[b*PP + p0];
            float e1 = d_energy[b*PP + p1];
            float m = fmaxf(e0, e1);
#pragma unroll
            for(int o=16;o;o>>=1) m = fmaxf(m, __shfl_xor_sync(0xffffffffu, m, o));
            if(lane==0) wred[wid] = m;
            __syncthreads();
            if(tid < 32){
                float v = (tid<16) ? wred[tid] : -3.4e38f;
#pragma unroll
                for(int o=8;o;o>>=1) v = fmaxf(v, __shfl_xor_sync(0xffffffffu, v, o));
                if(tid==0) wred[32] = v;
            }
            __syncthreads();
            float M = wred[32];
            float ex0 = expf(e0 - M) * d_mask[b*PP + p0];
            float ex1 = expf(e1 - M) * d_mask[b*PP + p1];
            float sv = ex0 + ex1;
#pragma unroll
            for(int o=16;o;o>>=1) sv += __shfl_xor_sync(0xffffffffu, sv, o);
            __syncthreads();
            if(lane==0) wred[wid] = sv;
            __syncthreads();
            if(tid < 32){
                float v = (tid<16) ? wred[tid] : 0.f;
#pragma unroll
                for(int o=8;o;o>>=1) v += __shfl_xor_sync(0xffffffffu, v, o);
                if(tid==0) wred[32] = v;
            }
            __syncthreads();
            float S = wred[32];
            float a0 = ex0 / (S + 1e-10f);
            float a1 = ex1 / (S + 1e-10f);
            d_asum[b*PP + p0] += a0;
            d_asum[b*PP + p1] += a1;
            out_alphas[((size_t)(b*TT + t))*PP + p0] = a0;
            out_alphas[((size_t)(b*TT + t))*PP + p1] = a1;

            // ---- compaction ----
            bool act0 = a0 > 0.02f, act1 = a1 > 0.02f;
            unsigned m0 = __ballot_sync(0xffffffffu, act0);
            unsigned m1 = __ballot_sync(0xffffffffu, act1);
            if(lane==0) wcnt[wid] = __popc(m0) + __popc(m1);
            if(tid < HID) hg[tid] = d_hid[(t+1)&1][b*HID + tid];  // hidden after GRU step t
            __syncthreads();
            if(tid < 16){
                int v = wcnt[tid], sc = v;
#pragma unroll
                for(int o=1;o<16;o<<=1){ int u=__shfl_up_sync(0x0000ffffu, sc, o); if(tid>=o) sc += u; }
                wcnt[tid] = sc - v;
                if(tid==15) nact_s = sc;
            }
            __syncthreads();
            int base = wcnt[wid];
            unsigned lm = (1u<<lane) - 1u;
            if(act0){ int idx = base + __popc(m0 & lm); if(idx<64){ pl[idx]=p0; wl[idx]=a0; } }
            if(act1){ int idx = base + __popc(m0) + __popc(m1 & lm); if(idx<64){ pl[idx]=p1; wl[idx]=a1; } }
            __syncthreads();

            // ---- state matvec + ctx gather partials ----
            {
                int j = tid & 255, part = tid >> 8;
                float s = 0.f;
#pragma unroll 4
                for(int c=part*128; c<part*128+128; c++)
                    s = fmaf(d_WstT[c*HID + j], hg[c], s);
                int n = nact_s < 64 ? nact_s : 64;
                for(int i=part; i<n; i+=2)
                    s = fmaf(wl[i], d_cnnW[((size_t)(b*PP + pl[i]))*HID + j], s);
                sacc[part][j] = s;
            }
            __syncthreads();
            if(tid < HID){
                float v = sacc[0][tid] + sacc[1][tid]
                        + bstate[tid] + bctx[tid]
                        + d_embwall[(size_t)(t*BB+b)*HID + tid];
                os[tid] = fmaxf(v, d_locw[b*HID + tid]);
            }
            __syncthreads();
            // ---- W_out + probs ----
            {
                int j2 = tid & 127, p4 = tid >> 7;
                float pr = 0.f;
                if(j2 < VOC){
#pragma unroll 4
                    for(int c=p4*64; c<p4*64+64; c++)
                        pr = fmaf(d_WoutT[c*VOC + j2], os[c], pr);
                }
                pp4[p4][j2] = pr;
            }
            __syncthreads();
            if(tid < VOC){
                out_probs[((size_t)(b*TT + t))*VOC + tid] =
                    bout[tid] + pp4[0][tid] + pp4[1][tid] + pp4[2][tid] + pp4[3][tid];
            }
        } else if(h>=1 && h<=8){
            if(t+1 < TT){ gru_full(t+1); query_q(t+1); }
        }
        if(t+1 < TT) bar();
    }
}

// ---------------- launch ----------------
extern "C" void kernel_launch(void* const* d_in, const int* in_sizes, int n_in,
                              void* d_out, int out_size){
    const float* cnn     = (const float*)d_in[0];
    const int*   labels  = (const int*)  d_in[1];
    const float* locp    = (const float*)d_in[2];
    const float* imask   = (const float*)d_in[3];
    const float* W_init  = (const float*)d_in[5];
    const float* b_init  = (const float*)d_in[6];
    const float* emb     = (const float*)d_in[7];
    const float* W_ih    = (const float*)d_in[8];
    const float* b_ih    = (const float*)d_in[9];
    const float* W_hh    = (const float*)d_in[10];
    const float* b_hh    = (const float*)d_in[11];
    const float* W_hq    = (const float*)d_in[12];
    const float* b_hq    = (const float*)d_in[13];
    const float* K_cov   = (const float*)d_in[14];
    const float* W_att   = (const float*)d_in[15];
    const float* W_ac    = (const float*)d_in[16];
    const float* b_ac    = (const float*)d_in[17];
    const float* K_enc   = (const float*)d_in[18];
    const float* b_enc   = (const float*)d_in[19];
    const float* W_state = (const float*)d_in[20];
    const float* b_state = (const float*)d_in[21];
    const float* W_embw  = (const float*)d_in[22];
    const float* b_embw  = (const float*)d_in[23];
    const float* W_ctx   = (const float*)d_in[24];
    const float* b_ctx   = (const float*)d_in[25];
    const float* W_out   = (const float*)d_in[26];
    const float* b_out   = (const float*)d_in[27];
    const float* W_loc   = (const float*)d_in[28];
    const float* b_loc   = (const float*)d_in[29];

    float* out_probs  = (float*)d_out;
    float* out_alphas = (float*)d_out + (size_t)BB*TT*VOC;

    k_preA<<<PA_TOT, 256>>>(imask, K_cov, labels, emb, W_hh, W_hq, W_state, W_out, cnn);
    k_preB<<<PB_TOT, 256>>>(cnn, K_enc, b_enc, W_ctx, W_ih, b_ih, W_embw, b_embw, W_att);
    k_preC<<<512, 256>>>(W_init, b_init, W_loc, b_loc, locp);
    k_loop<<<NB, 512>>>(W_ac, b_ac, b_hh, b_hq, b_state, b_ctx, b_out,
                        out_probs, out_alphas);
}

// round 9
// speedup vs baseline: 1.0717x; 1.0717x over previous
#include <cuda_runtime.h>
#include <math.h>

// ---------------- problem constants ----------------
#define BB   8
#define CC   684
#define HHD  16
#define WWD  64
#define PP   1024
#define TT   32
#define HID  256
#define ATT  512
#define COVD 512
#define VOC  111
#define LOCD 432
#define KC   11
#define RAT  16

typedef unsigned long long ull;

// ---------------- scratch ----------------
__device__ float d_mask[BB*PP];
__device__ float d_msum[BB];
__device__ float d_avg[BB*CC];
__device__ float d_hid0[BB*HID];
__device__ float d_hch[2][BB*HID];
__device__ float d_locw[BB*HID];
__device__ float d_kcovT[KC*KC*COVD];
__device__ float d_KfT[KC*KC*ATT];
__device__ float d_cnnT[(size_t)BB*PP*CC];
__device__ float d_ctrans[(size_t)BB*PP*ATT];
__device__ float d_cnnW[(size_t)BB*PP*HID];
__device__ float d_embseq[TT*BB*HID];
__device__ float d_giall[TT*BB*3*HID];
__device__ float d_embwall[TT*BB*HID];
__device__ float d_queryall[TT*BB*ATT];
__device__ float d_stall[TT*BB*HID];
__device__ float d_asum[2][BB*PP];
__device__ float d_energy[2][BB*PP];
__device__ float d_MS[2][BB*32];          // per (b,row): (max, expsum)
__device__ float d_Whh2[HID*3*HID];       // [c/2][row768][2]
__device__ float d_Whq2[HID*ATT];         // [c/2][q512][2]
__device__ float d_Wst2[HID*HID];         // [c/2][j256][2]
__device__ float d_WoutT[HID*VOC];        // [c][v]
__device__ unsigned d_bcnt[BB*32];        // loop barrier, padded
__device__ unsigned d_ccnt[BB*32];        // chain barrier, padded

// ---------------- helpers ----------------
__device__ __forceinline__ float warp_red(float s){
#pragma unroll
    for(int o=16;o;o>>=1) s += __shfl_down_sync(0xffffffffu, s, o);
    return s;
}
__device__ __forceinline__ ull pack2(float lo, float hi){
    ull r; asm("mov.b64 %0, {%1,%2};" : "=l"(r) : "f"(lo), "f"(hi)); return r;
}
__device__ __forceinline__ void fma2(ull &d, ull a, ull b){
    asm("fma.rn.f32x2 %0, %1, %2, %0;" : "+l"(d) : "l"(a), "l"(b));
}
__device__ __forceinline__ float2 unpack2(ull v){
    float2 f; asm("mov.b64 {%0,%1}, %2;" : "=f"(f.x), "=f"(f.y) : "l"(v)); return f;
}
__device__ __forceinline__ float tanha(float x){
    asm("tanh.approx.f32 %0, %0;" : "+f"(x)); return x;
}

// =================== Launch 0: k_preA ===================
#define PA_INIT  0
#define PA_CNNT  8
#define PA_KCOV  (PA_CNNT+5632)
#define PA_EMB   (PA_KCOV+242)
#define PA_WHH   (PA_EMB+256)
#define PA_WHQ   (PA_WHH+768)
#define PA_WST   (PA_WHQ+512)
#define PA_WOUT  (PA_WST+256)
#define PA_TOT   (PA_WOUT+112)

__global__ void __launch_bounds__(256) k_preA(
    const float* __restrict__ imask, const float* __restrict__ K_cov,
    const int*   __restrict__ labels,const float* __restrict__ emb,
    const float* __restrict__ W_hh,  const float* __restrict__ W_hq,
    const float* __restrict__ W_state,const float* __restrict__ W_out,
    const float* __restrict__ cnn)
{
    const int blk = blockIdx.x, tid = threadIdx.x;
    __shared__ float red[256];
    __shared__ float tile[32][33];

    if(blk < PA_CNNT){
        int b = blk;
        float s = 0.f;
        for(int i=tid;i<PP;i+=256){
            int hh = i>>6, ww = i&63;
            float m = imask[(size_t)b*(256*1024) + (size_t)(hh*RAT)*1024 + ww*RAT];
            d_mask[b*PP+i] = m;
            d_asum[0][b*PP+i] = 0.f;
            s += m;
        }
        red[tid]=s; __syncthreads();
        for(int o=128;o;o>>=1){ if(tid<o) red[tid]+=red[tid+o]; __syncthreads(); }
        if(tid==0){ d_msum[b]=red[0]; d_bcnt[b*32]=0u; d_ccnt[b*32]=0u; }
    } else if(blk < PA_KCOV){
        int idx = blk - PA_CNNT;
        int bb = idx / 704, rem = idx % 704;
        int c0 = (rem>>5)*32, p0 = (rem&31)*32;
        int tx = tid&31, ty = tid>>5;
#pragma unroll
        for(int pass=0;pass<4;pass++){
            int r = pass*8+ty;
            if(c0+r < CC) tile[r][tx] = cnn[((size_t)(bb*CC + c0+r))*PP + p0+tx];
        }
        __syncthreads();
#pragma unroll
        for(int pass=0;pass<4;pass++){
            int r = pass*8+ty;
            if(c0+tx < CC) d_cnnT[((size_t)(bb*PP + p0+r))*CC + c0+tx] = tile[tx][r];
        }
    } else if(blk < PA_EMB){
        int e = (blk-PA_KCOV)*256 + tid;
        if(e < COVD*KC*KC){
            int c = e/(KC*KC), ij = e - c*(KC*KC);
            d_kcovT[ij*COVD + c] = K_cov[e];
        }
    } else if(blk < PA_WHH){
        int e = (blk-PA_EMB)*256 + tid;
        int k = e & (HID-1);
        int tb = e >> 8;
        int b = tb & 7, t = tb >> 3;
        int lbl = (t==0) ? 1 : labels[b*TT + (t-1)];
        d_embseq[e] = emb[(size_t)lbl*HID + k];
    } else if(blk < PA_WHQ){
        int e = (blk-PA_WHH)*256 + tid;   // 768*256 source elems
        int r = e >> 8, c = e & 255;
        d_Whh2[(c>>1)*1536 + r*2 + (c&1)] = W_hh[e];
    } else if(blk < PA_WST){
        int e = (blk-PA_WHQ)*256 + tid;   // 512*256
        int q = e >> 8, c = e & 255;
        d_Whq2[(c>>1)*1024 + q*2 + (c&1)] = W_hq[e];
    } else if(blk < PA_WOUT){
        int e = (blk-PA_WST)*256 + tid;   // 256*256
        int j = e >> 8, c = e & 255;
        d_Wst2[(c>>1)*512 + j*2 + (c&1)] = W_state[e];
    } else {
        int e = (blk-PA_WOUT)*256 + tid;  // VOC*256
        if(e < VOC*HID){
            int v = e >> 8, c = e & 255;
            d_WoutT[c*VOC + v] = W_out[e];
        }
    }
}

// =================== Launch 1: k_preB (GEMMs) ===================
#define PB_CW  1024
#define PB_GI  1536
#define PB_EW  1584
#define PB_KF  1600
#define PB_AVG 1616
#define PB_TOT 2300

__device__ void gemm64(const float* __restrict__ A, int M, int K,
                       const float* __restrict__ Wt, const float* __restrict__ bias,
                       float* __restrict__ out, int N, int ptile, int ntile,
                       float2 (*As)[68], float (*Bs)[68])
{
    int pt = ptile*64, at = ntile*64;
    int tid = threadIdx.x;
    int tx = tid & 15, ty = tid >> 4;
    ull acc2[4][2];
#pragma unroll
    for(int i=0;i<4;i++){ acc2[i][0]=0ull; acc2[i][1]=0ull; }

    for(int c0=0;c0<K;c0+=16){
#pragma unroll
        for(int l=0;l<4;l++){
            int lin = tid + l*256;
            int k = lin & 15, r = lin >> 4;
            int c = c0 + k;
            float av = (c < K && pt+r < M) ? A[((size_t)(pt+r))*K + c] : 0.f;
            As[k][r] = make_float2(av, av);
            Bs[k][r] = (c < K) ? Wt[((size_t)(at+r))*K + c] : 0.f;
        }
        __syncthreads();
#pragma unroll
        for(int k=0;k<16;k++){
            ull ra2[4], rb2[2];
#pragma unroll
            for(int i=0;i<4;i++) ra2[i] = *(const ull*)&As[k][ty*4+i];
            rb2[0] = *(const ull*)&Bs[k][tx*4];
            rb2[1] = *(const ull*)&Bs[k][tx*4+2];
#pragma unroll
            for(int i=0;i<4;i++){
                fma2(acc2[i][0], ra2[i], rb2[0]);
                fma2(acc2[i][1], ra2[i], rb2[1]);
            }
        }
        __syncthreads();
    }
#pragma unroll
    for(int i=0;i<4;i++){
        int p = pt + ty*4 + i;
        if(p < M){
#pragma unroll
            for(int jp=0;jp<2;jp++){
                int aa = at + tx*4 + jp*2;
                float2 v = unpack2(acc2[i][jp]);
                float b0 = bias ? bias[aa]   : 0.f;
                float b1 = bias ? bias[aa+1] : 0.f;
                out[(size_t)p*N + aa]   = v.x + b0;
                out[(size_t)p*N + aa+1] = v.y + b1;
            }
        }
    }
}

__global__ void __launch_bounds__(256) k_preB(
    const float* __restrict__ cnn,
    const float* __restrict__ K_enc, const float* __restrict__ b_enc,
    const float* __restrict__ W_ctx,
    const float* __restrict__ W_ih,  const float* __restrict__ b_ih,
    const float* __restrict__ W_embw,const float* __restrict__ b_embw,
    const float* __restrict__ W_att)
{
    __shared__ float2 As[16][68];
    __shared__ float  Bs[16][68];
    const int blk = blockIdx.x;

    if(blk < PB_CW){
        int i = blk;
        gemm64(d_cnnT, BB*PP, CC, K_enc, b_enc, d_ctrans, ATT, i & 127, i >> 7, As, Bs);
    } else if(blk < PB_GI){
        int i = blk - PB_CW;
        gemm64(d_cnnT, BB*PP, CC, W_ctx, (const float*)0, d_cnnW, HID, i & 127, i >> 7, As, Bs);
    } else if(blk < PB_EW){
        int i = blk - PB_GI;
        gemm64(d_embseq, TT*BB, HID, W_ih, b_ih, d_giall, 3*HID, i & 3, i >> 2, As, Bs);
    } else if(blk < PB_KF){
        int i = blk - PB_EW;
        gemm64(d_embseq, TT*BB, HID, W_embw, b_embw, d_embwall, HID, i & 3, i >> 2, As, Bs);
    } else if(blk < PB_AVG){
        int i = blk - PB_KF;
        gemm64(d_kcovT, KC*KC, COVD, W_att, (const float*)0, d_KfT, ATT, i & 1, i >> 1, As, Bs);
    } else {
        int gw = (blk - PB_AVG)*8 + (threadIdx.x >> 5);
        int lane = threadIdx.x & 31;
        if(gw < BB*CC){
            int b = gw / CC;
            const float* x = cnn + (size_t)gw*PP;
            const float* m = d_mask + b*PP;
            float s = 0.f;
            for(int p=lane;p<PP;p+=32) s += x[p]*m[p];
            s = warp_red(s);
            if(lane==0) d_avg[gw] = s / d_msum[b];
        }
    }
}

// =================== Launch 2: k_preC ===================
__global__ void __launch_bounds__(256) k_preC(
    const float* __restrict__ W_init, const float* __restrict__ b_init,
    const float* __restrict__ W_loc,  const float* __restrict__ b_loc,
    const float* __restrict__ locp)
{
    int gw = blockIdx.x*8 + (threadIdx.x >> 5);
    int lane = threadIdx.x & 31;
    if(gw < BB*HID){
        int b = gw / HID, j = gw - b*HID;
        const float* wv = W_init + (size_t)j*CC;
        const float* av = d_avg + b*CC;
        float s = 0.f;
        for(int c=lane;c<CC;c+=32) s += wv[c]*av[c];
        s = warp_red(s);
        if(lane==0) d_hid0[gw] = tanhf(s + b_init[j]);
    } else if(gw < 2*BB*HID){
        int g2 = gw - BB*HID;
        int b = g2 / HID, j = g2 - b*HID;
        const float* wv = W_loc + (size_t)j*LOCD;
        const float* xv = locp + (size_t)b*LOCD;
        float s = 0.f;
        for(int c=lane;c<LOCD;c+=32) s += wv[c]*xv[c];
        s = warp_red(s);
        if(lane==0) d_locw[g2] = s + b_loc[j];
    }
}

// =================== Launch 3: k_chain (sequential GRU, 4 blocks/b) ===================
__global__ void __launch_bounds__(512,1) k_chain(
    const float* __restrict__ bhh,  const float* __restrict__ bhq,
    const float* __restrict__ bstate,const float* __restrict__ bctx)
{
    const int bid = blockIdx.x;
    const int b = bid >> 2, k = bid & 3;
    const int tid = threadIdx.x;
    unsigned bt = 0;

    __shared__ __align__(8) float hc[HID];
    __shared__ float gv[192];

    if(tid < HID) hc[tid] = d_hid0[b*HID + tid];
    __syncthreads();

    for(int t=0; t<TT; t++){
        const ull* h2 = (const ull*)hc;
        // gates: 3 gates x 64 j each (this block's j-range [k*64, k*64+64))
        if(tid < 192){
            int g = tid >> 6, jl = tid & 63;
            int row = g*HID + k*64 + jl;
            const ull* wp = (const ull*)d_Whh2;
            ull acc = 0ull;
#pragma unroll 8
            for(int c2=0;c2<128;c2++) fma2(acc, wp[c2*768 + row], h2[c2]);
            float2 v = unpack2(acc);
            gv[tid] = v.x + v.y;
        }
        __syncthreads();
        if(tid < 64){
            int j = k*64 + tid;
            float hr = bhh[j]       + gv[tid];
            float hz = bhh[HID+j]   + gv[64+tid];
            float hv = bhh[2*HID+j] + gv[128+tid];
            const float* gi = d_giall + (size_t)(t*BB+b)*3*HID;
            float r = 1.f/(1.f+expf(-(gi[j]+hr)));
            float z = 1.f/(1.f+expf(-(gi[HID+j]+hz)));
            float n = tanhf(gi[2*HID+j] + r*hv);
            d_hch[(t+1)&1][b*HID + j] = (1.f - z)*n + z*hc[j];
        }
        // per-b barrier over 4 blocks
        __syncthreads();
        bt += 4;
        if(tid==0){
            __threadfence();
            atomicAdd(&d_ccnt[b*32], 1u);
            while(*(volatile unsigned*)&d_ccnt[b*32] < bt) __nanosleep(16);
            __threadfence();
        }
        __syncthreads();
        if(tid < HID) hc[tid] = d_hch[(t+1)&1][b*HID + tid];
        __syncthreads();
        const ull* hn2 = (const ull*)hc;
        if(tid < 128){
            int q = k*128 + tid;
            const ull* wq = (const ull*)d_Whq2;
            ull acc = 0ull;
#pragma unroll 8
            for(int c2=0;c2<128;c2++) fma2(acc, wq[c2*512 + q], hn2[c2]);
            float2 v = unpack2(acc);
            d_queryall[(size_t)(t*BB+b)*ATT + q] = bhq[q] + v.x + v.y;
        } else if(tid < 192){
            int j = k*64 + (tid-128);
            const ull* ws = (const ull*)d_Wst2;
            ull acc = 0ull;
#pragma unroll 8
            for(int c2=0;c2<128;c2++) fma2(acc, ws[c2*256 + j], hn2[c2]);
            float2 v = unpack2(acc);
            d_stall[(size_t)(t*BB+b)*HID + j] = bstate[j] + bctx[j]
                + d_embwall[(size_t)(t*BB+b)*HID + j] + v.x + v.y;
        }
        __syncthreads();
    }
}

// =================== Launch 4: k_loop (persistent, 1 barrier/phase) ===================
__global__ void __launch_bounds__(512,1) k_loop(
    const float* __restrict__ Wac,   const float* __restrict__ bac,
    const float* __restrict__ bout,
    float* __restrict__ out_probs,   float* __restrict__ out_alphas)
{
    const int bid = blockIdx.x;       // 0..135
    const int b = bid / 17;
    const int h = bid - b*17;         // 0..16; 16 = P block
    const int tid = threadIdx.x;
    const int lane = tid & 31, wid = tid >> 5;
    unsigned bt = 0;

    __shared__ float2 taps2[KC*74];
    __shared__ float  spart[4][4][16];
    __shared__ float  wred[4];
    __shared__ int    wcnt[16];
    __shared__ int    pl[64];
    __shared__ float  wl[64];
    __shared__ int    nact_s;
    __shared__ float  sacc[2][HID];
    __shared__ float  os[HID];
    __shared__ float  pp4[4][128];

    const float bac0 = bac[0];

    for(int p=0; p<=TT; p++){
        // ---- combine per-row (M,S) from previous phase ----
        float M = -3.4e38f, S1e = 1e-10f;
        if(p > 0){
            const float* ms = d_MS[(p-1)&1] + b*32;
            float s = 0.f;
#pragma unroll
            for(int r=0;r<16;r++) M = fmaxf(M, ms[2*r]);
#pragma unroll
            for(int r=0;r<16;r++) s += expf(ms[2*r]-M)*ms[2*r+1];
            S1e = s + 1e-10f;
        }

        if(h < 16){
            // ---- own-row alpha outputs + asum update ----
            if(p > 0){
                if(tid < 64){
                    int px = b*PP + h*WWD + tid;
                    float e = d_energy[(p-1)&1][px];
                    float a = expf(e - M)*d_mask[px]/S1e;
                    out_alphas[((size_t)(b*TT + (p-1)))*PP + h*WWD + tid] = a;
                    d_asum[p&1][px] = d_asum[(p-1)&1][px] + a;
                }
                if(p < TT){
                    // taps = asum_{p-1} + alpha(p-1), rows h-5..h+5
                    for(int idx=tid; idx<KC*74; idx+=512){
                        int i = idx/74, w2 = idx - i*74;
                        int r = h + i - 5, wg = w2 - 5;
                        float v = 0.f;
                        if(r>=0 && r<HHD && wg>=0 && wg<WWD){
                            int px = b*PP + r*WWD + wg;
                            float e = d_energy[(p-1)&1][px];
                            float a = expf(e - M)*d_mask[px]/S1e;
                            v = d_asum[(p-1)&1][px] + a;
                        }
                        taps2[idx] = make_float2(v, v);
                    }
                    __syncthreads();
                }
            }

            if(p < TT){
                // ---- conv + energy ----
                const int ag = tid & 127, wg = tid >> 7;
                const int a0 = ag << 2,  w0 = wg << 4;
                ull acc01[16], acc23[16];
#pragma unroll
                for(int w=0;w<16;w++){ acc01[w]=0ull; acc23[w]=0ull; }

                if(p > 0){
#pragma unroll 1
                    for(int i=0;i<KC;i++){
                        const ull* trow = (const ull*)(&taps2[i*74 + w0]);
#pragma unroll
                        for(int j=0;j<KC;j++){
                            float4 kv = *(const float4*)(d_KfT + (i*KC+j)*ATT + a0);
                            ull k01 = pack2(kv.x, kv.y);
                            ull k23 = pack2(kv.z, kv.w);
#pragma unroll
                            for(int w=0;w<16;w++){
                                ull tp = trow[j + w];
                                fma2(acc01[w], k01, tp);
                                fma2(acc23[w], k23, tp);
                            }
                        }
                    }
                }

                float4 q4  = *(const float4*)(d_queryall + (size_t)(p*BB+b)*ATT + a0);
                float4 wa4 = *(const float4*)(Wac + a0);
                const float* ctbase = d_ctrans + ((size_t)(b*PP + h*WWD + w0))*ATT + a0;
                int wiw = (tid >> 5) & 3;
#pragma unroll
                for(int w=0;w<16;w++){
                    float4 ct = *(const float4*)(ctbase + (size_t)w*ATT);
                    float2 a01 = unpack2(acc01[w]);
                    float2 a23 = unpack2(acc23[w]);
                    float v = wa4.x * tanha(q4.x + a01.x + ct.x)
                            + wa4.y * tanha(q4.y + a01.y + ct.y)
                            + wa4.z * tanha(q4.z + a23.x + ct.z)
                            + wa4.w * tanha(q4.w + a23.y + ct.w);
#pragma unroll
                    for(int o=16;o;o>>=1) v += __shfl_down_sync(0xffffffffu, v, o);
                    if(lane==0) spart[wg][wiw][w] = v;
                }
                __syncthreads();
                float ev = 0.f;
                if(tid < 64){
                    int wgo = tid >> 4, wlx = tid & 15;
                    ev = spart[wgo][0][wlx] + spart[wgo][1][wlx]
                       + spart[wgo][2][wlx] + spart[wgo][3][wlx] + bac0;
                    d_energy[p&1][b*PP + h*WWD + tid] = ev;
                    float m = ev;
#pragma unroll
                    for(int o=16;o;o>>=1) m = fmaxf(m, __shfl_xor_sync(0xffffffffu, m, o));
                    if(lane==0) wred[wid] = m;
                }
                __syncthreads();
                float Mr = fmaxf(wred[0], wred[1]);
                if(tid < 64){
                    float s = expf(ev - Mr)*d_mask[b*PP + h*WWD + tid];
#pragma unroll
                    for(int o=16;o;o>>=1) s += __shfl_xor_sync(0xffffffffu, s, o);
                    if(lane==0) wred[2+wid] = s;
                }
                __syncthreads();
                if(tid==0){
                    float* msd = d_MS[p&1] + b*32 + h*2;
                    msd[0] = Mr; msd[1] = wred[2] + wred[3];
                }
            }
        } else {
            // ================= P block: ctx + probs for t' = p-1 =================
            if(p > 0){
                int t2 = p-1;
                int p0 = tid, p1 = tid + 512;
                float e0 = d_energy[(p-1)&1][b*PP + p0];
                float e1 = d_energy[(p-1)&1][b*PP + p1];
                float a0 = expf(e0 - M)*d_mask[b*PP + p0]/S1e;
                float a1 = expf(e1 - M)*d_mask[b*PP + p1]/S1e;

                bool act0 = a0 > 0.02f, act1 = a1 > 0.02f;
                unsigned m0 = __ballot_sync(0xffffffffu, act0);
                unsigned m1 = __ballot_sync(0xffffffffu, act1);
                if(lane==0) wcnt[wid] = __popc(m0) + __popc(m1);
                __syncthreads();
                if(tid < 16){
                    int v = wcnt[tid], sc = v;
#pragma unroll
                    for(int o=1;o<16;o<<=1){ int u=__shfl_up_sync(0x0000ffffu, sc, o); if(tid>=o) sc += u; }
                    wcnt[tid] = sc - v;
                    if(tid==15) nact_s = sc;
                }
                __syncthreads();
                int base = wcnt[wid];
                unsigned lm = (1u<<lane) - 1u;
                if(act0){ int idx = base + __popc(m0 & lm); if(idx<64){ pl[idx]=p0; wl[idx]=a0; } }
                if(act1){ int idx = base + __popc(m0) + __popc(m1 & lm); if(idx<64){ pl[idx]=p1; wl[idx]=a1; } }
                __syncthreads();

                // ctx gather partials
                {
                    int j = tid & 255, part = tid >> 8;
                    float s = 0.f;
                    int n = nact_s < 64 ? nact_s : 64;
                    for(int i=part; i<n; i+=2)
                        s = fmaf(wl[i], d_cnnW[((size_t)(b*PP + pl[i]))*HID + j], s);
                    sacc[part][j] = s;
                }
                __syncthreads();
                if(tid < HID){
                    float v = sacc[0][tid] + sacc[1][tid]
                            + d_stall[(size_t)(t2*BB+b)*HID + tid];
                    os[tid] = fmaxf(v, d_locw[b*HID + tid]);
                }
                __syncthreads();
                {
                    int j2 = tid & 127, p4 = tid >> 7;
                    float pr = 0.f;
                    if(j2 < VOC){
#pragma unroll 4
                        for(int c=p4*64; c<p4*64+64; c++)
                            pr = fmaf(d_WoutT[c*VOC + j2], os[c], pr);
                    }
                    pp4[p4][j2] = pr;
                }
                __syncthreads();
                if(tid < VOC){
                    out_probs[((size_t)(b*TT + t2))*VOC + tid] =
                        bout[tid] + pp4[0][tid] + pp4[1][tid] + pp4[2][tid] + pp4[3][tid];
                }
            }
        }

        // ---- single per-b barrier (17 blocks) ----
        if(p < TT){
            __syncthreads();
            bt += 17;
            if(tid==0){
                __threadfence();
                atomicAdd(&d_bcnt[b*32], 1u);
                while(*(volatile unsigned*)&d_bcnt[b*32] < bt) __nanosleep(16);
                __threadfence();
            }
            __syncthreads();
        }
    }
}

// ---------------- launch ----------------
extern "C" void kernel_launch(void* const* d_in, const int* in_sizes, int n_in,
                              void* d_out, int out_size){
    const float* cnn     = (const float*)d_in[0];
    const int*   labels  = (const int*)  d_in[1];
    const float* locp    = (const float*)d_in[2];
    const float* imask   = (const float*)d_in[3];
    const float* W_init  = (const float*)d_in[5];
    const float* b_init  = (const float*)d_in[6];
    const float* emb     = (const float*)d_in[7];
    const float* W_ih    = (const float*)d_in[8];
    const float* b_ih    = (const float*)d_in[9];
    const float* W_hh    = (const float*)d_in[10];
    const float* b_hh    = (const float*)d_in[11];
    const float* W_hq    = (const float*)d_in[12];
    const float* b_hq    = (const float*)d_in[13];
    const float* K_cov   = (const float*)d_in[14];
    const float* W_att   = (const float*)d_in[15];
    const float* W_ac    = (const float*)d_in[16];
    const float* b_ac    = (const float*)d_in[17];
    const float* K_enc   = (const float*)d_in[18];
    const float* b_enc   = (const float*)d_in[19];
    const float* W_state = (const float*)d_in[20];
    const float* b_state = (const float*)d_in[21];
    const float* W_embw  = (const float*)d_in[22];
    const float* b_embw  = (const float*)d_in[23];
    const float* W_ctx   = (const float*)d_in[24];
    const float* b_ctx   = (const float*)d_in[25];
    const float* W_out   = (const float*)d_in[26];
    const float* b_out   = (const float*)d_in[27];
    const float* W_loc   = (const float*)d_in[28];
    const float* b_loc   = (const float*)d_in[29];

    float* out_probs  = (float*)d_out;
    float* out_alphas = (float*)d_out + (size_t)BB*TT*VOC;

    k_preA<<<PA_TOT, 256>>>(imask, K_cov, labels, emb, W_hh, W_hq, W_state, W_out, cnn);
    k_preB<<<PB_TOT, 256>>>(cnn, K_enc, b_enc, W_ctx, W_ih, b_ih, W_embw, b_embw, W_att);
    k_preC<<<512, 256>>>(W_init, b_init, W_loc, b_loc, locp);
    k_chain<<<BB*4, 512>>>(b_hh, b_hq, b_state, b_ctx);
    k_loop<<<BB*17, 512>>>(W_ac, b_ac, b_out, out_probs, out_alphas);
}

// round 10
// speedup vs baseline: 1.2762x; 1.1908x over previous
#include <cuda_runtime.h>
#include <math.h>

// ---------------- problem constants ----------------
#define BB   8
#define CC   684
#define HHD  16
#define WWD  64
#define PP   1024
#define TT   32
#define HID  256
#define ATT  512
#define COVD 512
#define VOC  111
#define LOCD 432
#define KC   11
#define RAT  16

typedef unsigned long long ull;

// ---------------- scratch ----------------
__device__ float d_mask[BB*PP];
__device__ float d_msum[BB];
__device__ float d_avg[BB*CC];
__device__ float d_hid0[BB*HID];
__device__ float d_locw[BB*HID];
__device__ float d_kcovT[KC*KC*COVD];
__device__ float d_KfT[KC*KC*ATT];
__device__ float d_cnnT[(size_t)BB*PP*CC];
__device__ float d_ctrans[(size_t)BB*PP*ATT];
__device__ float d_cnnW[(size_t)BB*PP*HID];
__device__ float d_embseq[TT*BB*HID];
__device__ float d_giall[TT*BB*3*HID];
__device__ float d_embwall[TT*BB*HID];
__device__ float d_queryall[TT*BB*ATT];
__device__ float d_stall[TT*BB*HID];
__device__ float d_asum[2][BB*PP];
__device__ float d_energy[2][BB*PP];
__device__ float d_MS[2][BB*32];          // per (b,row): (max, expsum)
__device__ float d_Whh2[HID*3*HID];       // [c/2][row768][2]
__device__ float d_Whq2[HID*ATT];         // [c/2][q512][2]
__device__ float d_Wst2[HID*HID];         // [c/2][j256][2]
__device__ float d_WoutT[HID*VOC];        // [c][v]
__device__ unsigned d_bcnt[BB*32];        // loop barrier, padded
__device__ unsigned d_qflag[BB*32];       // chain progress flag, padded

// ---------------- helpers ----------------
__device__ __forceinline__ float warp_red(float s){
#pragma unroll
    for(int o=16;o;o>>=1) s += __shfl_down_sync(0xffffffffu, s, o);
    return s;
}
__device__ __forceinline__ ull pack2(float lo, float hi){
    ull r; asm("mov.b64 %0, {%1,%2};" : "=l"(r) : "f"(lo), "f"(hi)); return r;
}
__device__ __forceinline__ void fma2(ull &d, ull a, ull b){
    asm("fma.rn.f32x2 %0, %1, %2, %0;" : "+l"(d) : "l"(a), "l"(b));
}
__device__ __forceinline__ float2 unpack2(ull v){
    float2 f; asm("mov.b64 {%0,%1}, %2;" : "=f"(f.x), "=f"(f.y) : "l"(v)); return f;
}
__device__ __forceinline__ float tanha(float x){
    asm("tanh.approx.f32 %0, %0;" : "+f"(x)); return x;
}

// =================== Launch 0: k_preA ===================
#define PA_INIT  0
#define PA_CNNT  8
#define PA_KCOV  (PA_CNNT+5632)
#define PA_EMB   (PA_KCOV+242)
#define PA_WHH   (PA_EMB+256)
#define PA_WHQ   (PA_WHH+768)
#define PA_WST   (PA_WHQ+512)
#define PA_WOUT  (PA_WST+256)
#define PA_TOT   (PA_WOUT+112)

__global__ void __launch_bounds__(256) k_preA(
    const float* __restrict__ imask, const float* __restrict__ K_cov,
    const int*   __restrict__ labels,const float* __restrict__ emb,
    const float* __restrict__ W_hh,  const float* __restrict__ W_hq,
    const float* __restrict__ W_state,const float* __restrict__ W_out,
    const float* __restrict__ cnn)
{
    const int blk = blockIdx.x, tid = threadIdx.x;
    __shared__ float red[256];
    __shared__ float tile[32][33];

    if(blk < PA_CNNT){
        int b = blk;
        float s = 0.f;
        for(int i=tid;i<PP;i+=256){
            int hh = i>>6, ww = i&63;
            float m = imask[(size_t)b*(256*1024) + (size_t)(hh*RAT)*1024 + ww*RAT];
            d_mask[b*PP+i] = m;
            d_asum[0][b*PP+i] = 0.f;
            s += m;
        }
        red[tid]=s; __syncthreads();
        for(int o=128;o;o>>=1){ if(tid<o) red[tid]+=red[tid+o]; __syncthreads(); }
        if(tid==0){ d_msum[b]=red[0]; d_bcnt[b*32]=0u; d_qflag[b*32]=0u; }
    } else if(blk < PA_KCOV){
        int idx = blk - PA_CNNT;
        int bb = idx / 704, rem = idx % 704;
        int c0 = (rem>>5)*32, p0 = (rem&31)*32;
        int tx = tid&31, ty = tid>>5;
#pragma unroll
        for(int pass=0;pass<4;pass++){
            int r = pass*8+ty;
            if(c0+r < CC) tile[r][tx] = cnn[((size_t)(bb*CC + c0+r))*PP + p0+tx];
        }
        __syncthreads();
#pragma unroll
        for(int pass=0;pass<4;pass++){
            int r = pass*8+ty;
            if(c0+tx < CC) d_cnnT[((size_t)(bb*PP + p0+r))*CC + c0+tx] = tile[tx][r];
        }
    } else if(blk < PA_EMB){
        int e = (blk-PA_KCOV)*256 + tid;
        if(e < COVD*KC*KC){
            int c = e/(KC*KC), ij = e - c*(KC*KC);
            d_kcovT[ij*COVD + c] = K_cov[e];
        }
    } else if(blk < PA_WHH){
        int e = (blk-PA_EMB)*256 + tid;
        int k = e & (HID-1);
        int tb = e >> 8;
        int b = tb & 7, t = tb >> 3;
        int lbl = (t==0) ? 1 : labels[b*TT + (t-1)];
        d_embseq[e] = emb[(size_t)lbl*HID + k];
    } else if(blk < PA_WHQ){
        int e = (blk-PA_WHH)*256 + tid;   // 768*256 source elems
        int r = e >> 8, c = e & 255;
        d_Whh2[(c>>1)*1536 + r*2 + (c&1)] = W_hh[e];
    } else if(blk < PA_WST){
        int e = (blk-PA_WHQ)*256 + tid;   // 512*256
        int q = e >> 8, c = e & 255;
        d_Whq2[(c>>1)*1024 + q*2 + (c&1)] = W_hq[e];
    } else if(blk < PA_WOUT){
        int e = (blk-PA_WST)*256 + tid;   // 256*256
        int j = e >> 8, c = e & 255;
        d_Wst2[(c>>1)*512 + j*2 + (c&1)] = W_state[e];
    } else {
        int e = (blk-PA_WOUT)*256 + tid;  // VOC*256
        if(e < VOC*HID){
            int v = e >> 8, c = e & 255;
            d_WoutT[c*VOC + v] = W_out[e];
        }
    }
}

// =================== Launch 1: k_preB (GEMMs) ===================
#define PB_CW  1024
#define PB_GI  1536
#define PB_EW  1584
#define PB_KF  1600
#define PB_AVG 1616
#define PB_TOT 2300

__device__ void gemm64(const float* __restrict__ A, int M, int K,
                       const float* __restrict__ Wt, const float* __restrict__ bias,
                       float* __restrict__ out, int N, int ptile, int ntile,
                       float2 (*As)[68], float (*Bs)[68])
{
    int pt = ptile*64, at = ntile*64;
    int tid = threadIdx.x;
    int tx = tid & 15, ty = tid >> 4;
    ull acc2[4][2];
#pragma unroll
    for(int i=0;i<4;i++){ acc2[i][0]=0ull; acc2[i][1]=0ull; }

    for(int c0=0;c0<K;c0+=16){
#pragma unroll
        for(int l=0;l<4;l++){
            int lin = tid + l*256;
            int k = lin & 15, r = lin >> 4;
            int c = c0 + k;
            float av = (c < K && pt+r < M) ? A[((size_t)(pt+r))*K + c] : 0.f;
            As[k][r] = make_float2(av, av);
            Bs[k][r] = (c < K) ? Wt[((size_t)(at+r))*K + c] : 0.f;
        }
        __syncthreads();
#pragma unroll
        for(int k=0;k<16;k++){
            ull ra2[4], rb2[2];
#pragma unroll
            for(int i=0;i<4;i++) ra2[i] = *(const ull*)&As[k][ty*4+i];
            rb2[0] = *(const ull*)&Bs[k][tx*4];
            rb2[1] = *(const ull*)&Bs[k][tx*4+2];
#pragma unroll
            for(int i=0;i<4;i++){
                fma2(acc2[i][0], ra2[i], rb2[0]);
                fma2(acc2[i][1], ra2[i], rb2[1]);
            }
        }
        __syncthreads();
    }
#pragma unroll
    for(int i=0;i<4;i++){
        int p = pt + ty*4 + i;
        if(p < M){
#pragma unroll
            for(int jp=0;jp<2;jp++){
                int aa = at + tx*4 + jp*2;
                float2 v = unpack2(acc2[i][jp]);
                float b0 = bias ? bias[aa]   : 0.f;
                float b1 = bias ? bias[aa+1] : 0.f;
                out[(size_t)p*N + aa]   = v.x + b0;
                out[(size_t)p*N + aa+1] = v.y + b1;
            }
        }
    }
}

__global__ void __launch_bounds__(256) k_preB(
    const float* __restrict__ cnn,
    const float* __restrict__ K_enc, const float* __restrict__ b_enc,
    const float* __restrict__ W_ctx,
    const float* __restrict__ W_ih,  const float* __restrict__ b_ih,
    const float* __restrict__ W_embw,const float* __restrict__ b_embw,
    const float* __restrict__ W_att)
{
    __shared__ float2 As[16][68];
    __shared__ float  Bs[16][68];
    const int blk = blockIdx.x;

    if(blk < PB_CW){
        int i = blk;
        gemm64(d_cnnT, BB*PP, CC, K_enc, b_enc, d_ctrans, ATT, i & 127, i >> 7, As, Bs);
    } else if(blk < PB_GI){
        int i = blk - PB_CW;
        gemm64(d_cnnT, BB*PP, CC, W_ctx, (const float*)0, d_cnnW, HID, i & 127, i >> 7, As, Bs);
    } else if(blk < PB_EW){
        int i = blk - PB_GI;
        gemm64(d_embseq, TT*BB, HID, W_ih, b_ih, d_giall, 3*HID, i & 3, i >> 2, As, Bs);
    } else if(blk < PB_KF){
        int i = blk - PB_EW;
        gemm64(d_embseq, TT*BB, HID, W_embw, b_embw, d_embwall, HID, i & 3, i >> 2, As, Bs);
    } else if(blk < PB_AVG){
        int i = blk - PB_KF;
        gemm64(d_kcovT, KC*KC, COVD, W_att, (const float*)0, d_KfT, ATT, i & 1, i >> 1, As, Bs);
    } else {
        int gw = (blk - PB_AVG)*8 + (threadIdx.x >> 5);
        int lane = threadIdx.x & 31;
        if(gw < BB*CC){
            int b = gw / CC;
            const float* x = cnn + (size_t)gw*PP;
            const float* m = d_mask + b*PP;
            float s = 0.f;
            for(int p=lane;p<PP;p+=32) s += x[p]*m[p];
            s = warp_red(s);
            if(lane==0) d_avg[gw] = s / d_msum[b];
        }
    }
}

// =================== Launch 2: k_preC ===================
__global__ void __launch_bounds__(256) k_preC(
    const float* __restrict__ W_init, const float* __restrict__ b_init,
    const float* __restrict__ W_loc,  const float* __restrict__ b_loc,
    const float* __restrict__ locp)
{
    int gw = blockIdx.x*8 + (threadIdx.x >> 5);
    int lane = threadIdx.x & 31;
    if(gw < BB*HID){
        int b = gw / HID, j = gw - b*HID;
        const float* wv = W_init + (size_t)j*CC;
        const float* av = d_avg + b*CC;
        float s = 0.f;
        for(int c=lane;c<CC;c+=32) s += wv[c]*av[c];
        s = warp_red(s);
        if(lane==0) d_hid0[gw] = tanhf(s + b_init[j]);
    } else if(gw < 2*BB*HID){
        int g2 = gw - BB*HID;
        int b = g2 / HID, j = g2 - b*HID;
        const float* wv = W_loc + (size_t)j*LOCD;
        const float* xv = locp + (size_t)b*LOCD;
        float s = 0.f;
        for(int c=lane;c<LOCD;c+=32) s += wv[c]*xv[c];
        s = warp_red(s);
        if(lane==0) d_locw[g2] = s + b_loc[j];
    }
}

// =================== Launch 3: k_loop (persistent; chain fused as producer) ===================
__global__ void __launch_bounds__(512,1) k_loop(
    const float* __restrict__ Wac,   const float* __restrict__ bac,
    const float* __restrict__ bout,
    const float* __restrict__ bhh,   const float* __restrict__ bhq,
    const float* __restrict__ bstate,const float* __restrict__ bctx,
    float* __restrict__ out_probs,   float* __restrict__ out_alphas)
{
    const int bid = blockIdx.x;       // 0..143
    const int b = bid / 18;
    const int h = bid - b*18;         // 0..15 E rows; 16 = P block; 17 = chain producer
    const int tid = threadIdx.x;
    const int lane = tid & 31, wid = tid >> 5;
    unsigned bt = 0;

    __shared__ float2 taps2[KC*74];
    __shared__ float  spart[4][4][16];
    __shared__ float  wred[4];
    __shared__ int    wcnt[16];
    __shared__ int    pl[64];
    __shared__ float  wl[64];
    __shared__ int    nact_s;
    __shared__ float  sacc[2][HID];
    __shared__ float  os[HID];
    __shared__ float  pp4[4][128];
    __shared__ __align__(8) float hc[HID];
    __shared__ float  gv[3*HID];

    const float bac0 = bac[0];

    // ================= chain producer block =================
    if(h == 17){
        if(tid < HID) hc[tid] = d_hid0[b*HID + tid];
        __syncthreads();
        for(int t=0; t<TT; t++){
            const ull* h2 = (const ull*)hc;
            // gate matvec: rows 0..511 (r,z) + rows 512..767 (n) for tid<256
            {
                int r0 = tid;
                int r1 = 512 + (tid & 255);
                bool two = (tid < 256);
                ull a0=0ull, a1=0ull;
                const ull* wp = (const ull*)d_Whh2;
#pragma unroll 16
                for(int c2=0;c2<128;c2++){
                    ull hcv = h2[c2];
                    fma2(a0, wp[c2*768 + r0], hcv);
                    if(two) fma2(a1, wp[c2*768 + r1], hcv);
                }
                float2 v0 = unpack2(a0); gv[r0] = v0.x + v0.y;
                if(two){ float2 v1 = unpack2(a1); gv[r1] = v1.x + v1.y; }
            }
            __syncthreads();
            if(tid < HID){
                int j = tid;
                float hr = bhh[j]       + gv[j];
                float hz = bhh[HID+j]   + gv[HID+j];
                float hv = bhh[2*HID+j] + gv[2*HID+j];
                const float* gi = d_giall + (size_t)(t*BB+b)*3*HID;
                float r = 1.f/(1.f+expf(-(gi[j]+hr)));
                float z = 1.f/(1.f+expf(-(gi[HID+j]+hz)));
                float n = tanhf(gi[2*HID+j] + r*hv);
                gv[j] = (1.f - z)*n + z*hc[j];
            }
            __syncthreads();
            if(tid < HID) hc[tid] = gv[tid];
            __syncthreads();
            const ull* hn2 = (const ull*)hc;
            {
                int q = tid;
                int j = tid & 255;
                bool st = (tid < 256);
                ull aq = 0ull, as2 = 0ull;
                const ull* wq = (const ull*)d_Whq2;
                const ull* ws = (const ull*)d_Wst2;
#pragma unroll 16
                for(int c2=0;c2<128;c2++){
                    ull hcv = hn2[c2];
                    fma2(aq, wq[c2*512 + q], hcv);
                    if(st) fma2(as2, ws[c2*256 + j], hcv);
                }
                float2 vq = unpack2(aq);
                d_queryall[(size_t)(t*BB+b)*ATT + q] = bhq[q] + vq.x + vq.y;
                if(st){
                    float2 vs = unpack2(as2);
                    d_stall[(size_t)(t*BB+b)*HID + j] = bstate[j] + bctx[j]
                        + d_embwall[(size_t)(t*BB+b)*HID + j] + vs.x + vs.y;
                }
            }
            __threadfence();           // release: all stores visible before flag
            __syncthreads();
            if(tid==0) *((volatile unsigned*)&d_qflag[b*32]) = (unsigned)(t+1);
        }
        return;
    }

    // ================= E / P blocks =================
    for(int p=0; p<=TT; p++){
        // ---- combine per-row (M,S) from previous phase ----
        float M = -3.4e38f, S1e = 1e-10f;
        if(p > 0){
            const float* ms = d_MS[(p-1)&1] + b*32;
            float s = 0.f;
#pragma unroll
            for(int r=0;r<16;r++) M = fmaxf(M, ms[2*r]);
#pragma unroll
            for(int r=0;r<16;r++) s += expf(ms[2*r]-M)*ms[2*r+1];
            S1e = s + 1e-10f;
        }

        if(h < 16){
            if(p > 0){
                if(tid < 64){
                    int px = b*PP + h*WWD + tid;
                    float e = d_energy[(p-1)&1][px];
                    float a = expf(e - M)*d_mask[px]/S1e;
                    out_alphas[((size_t)(b*TT + (p-1)))*PP + h*WWD + tid] = a;
                    d_asum[p&1][px] = d_asum[(p-1)&1][px] + a;
                }
                if(p < TT){
                    for(int idx=tid; idx<KC*74; idx+=512){
                        int i = idx/74, w2 = idx - i*74;
                        int r = h + i - 5, wg = w2 - 5;
                        float v = 0.f;
                        if(r>=0 && r<HHD && wg>=0 && wg<WWD){
                            int px = b*PP + r*WWD + wg;
                            float e = d_energy[(p-1)&1][px];
                            float a = expf(e - M)*d_mask[px]/S1e;
                            v = d_asum[(p-1)&1][px] + a;
                        }
                        taps2[idx] = make_float2(v, v);
                    }
                    __syncthreads();
                }
            }

            if(p < TT){
                const int ag = tid & 127, wg = tid >> 7;
                const int a0 = ag << 2,  w0 = wg << 4;
                ull acc01[16], acc23[16];
#pragma unroll
                for(int w=0;w<16;w++){ acc01[w]=0ull; acc23[w]=0ull; }

                if(p > 0){
#pragma unroll 1
                    for(int i=0;i<KC;i++){
                        const ull* trow = (const ull*)(&taps2[i*74 + w0]);
#pragma unroll
                        for(int j=0;j<KC;j++){
                            float4 kv = *(const float4*)(d_KfT + (i*KC+j)*ATT + a0);
                            ull k01 = pack2(kv.x, kv.y);
                            ull k23 = pack2(kv.z, kv.w);
#pragma unroll
                            for(int w=0;w<16;w++){
                                ull tp = trow[j + w];
                                fma2(acc01[w], k01, tp);
                                fma2(acc23[w], k23, tp);
                            }
                        }
                    }
                }

                // ---- wait for chain to publish query(p) (usually already done) ----
                if(tid==0){
                    while(*((volatile unsigned*)&d_qflag[b*32]) < (unsigned)(p+1))
                        __nanosleep(32);
                }
                __syncthreads();

                float4 q4  = *(const float4*)(d_queryall + (size_t)(p*BB+b)*ATT + a0);
                float4 wa4 = *(const float4*)(Wac + a0);
                const float* ctbase = d_ctrans + ((size_t)(b*PP + h*WWD + w0))*ATT + a0;
                int wiw = (tid >> 5) & 3;
#pragma unroll
                for(int w=0;w<16;w++){
                    float4 ct = *(const float4*)(ctbase + (size_t)w*ATT);
                    float2 a01 = unpack2(acc01[w]);
                    float2 a23 = unpack2(acc23[w]);
                    float v = wa4.x * tanha(q4.x + a01.x + ct.x)
                            + wa4.y * tanha(q4.y + a01.y + ct.y)
                            + wa4.z * tanha(q4.z + a23.x + ct.z)
                            + wa4.w * tanha(q4.w + a23.y + ct.w);
#pragma unroll
                    for(int o=16;o;o>>=1) v += __shfl_down_sync(0xffffffffu, v, o);
                    if(lane==0) spart[wg][wiw][w] = v;
                }
                __syncthreads();
                float ev = 0.f;
                if(tid < 64){
                    int wgo = tid >> 4, wlx = tid & 15;
                    ev = spart[wgo][0][wlx] + spart[wgo][1][wlx]
                       + spart[wgo][2][wlx] + spart[wgo][3][wlx] + bac0;
                    d_energy[p&1][b*PP + h*WWD + tid] = ev;
                    float m = ev;
#pragma unroll
                    for(int o=16;o;o>>=1) m = fmaxf(m, __shfl_xor_sync(0xffffffffu, m, o));
                    if(lane==0) wred[wid] = m;
                }
                __syncthreads();
                float Mr = fmaxf(wred[0], wred[1]);
                if(tid < 64){
                    float s = expf(ev - Mr)*d_mask[b*PP + h*WWD + tid];
#pragma unroll
                    for(int o=16;o;o>>=1) s += __shfl_xor_sync(0xffffffffu, s, o);
                    if(lane==0) wred[2+wid] = s;
                }
                __syncthreads();
                if(tid==0){
                    float* msd = d_MS[p&1] + b*32 + h*2;
                    msd[0] = Mr; msd[1] = wred[2] + wred[3];
                }
            }
        } else {
            // ================= P block: ctx + probs for t' = p-1 =================
            if(p > 0){
                int t2 = p-1;
                // stall(t2) requires flag >= p (guaranteed by E(p-1) + barrier; cheap check)
                if(tid==0){
                    while(*((volatile unsigned*)&d_qflag[b*32]) < (unsigned)p)
                        __nanosleep(32);
                }
                __syncthreads();

                int p0 = tid, p1 = tid + 512;
                float e0 = d_energy[(p-1)&1][b*PP + p0];
                float e1 = d_energy[(p-1)&1][b*PP + p1];
                float a0 = expf(e0 - M)*d_mask[b*PP + p0]/S1e;
                float a1 = expf(e1 - M)*d_mask[b*PP + p1]/S1e;

                bool act0 = a0 > 0.02f, act1 = a1 > 0.02f;
                unsigned m0 = __ballot_sync(0xffffffffu, act0);
                unsigned m1 = __ballot_sync(0xffffffffu, act1);
                if(lane==0) wcnt[wid] = __popc(m0) + __popc(m1);
                __syncthreads();
                if(tid < 16){
                    int v = wcnt[tid], sc = v;
#pragma unroll
                    for(int o=1;o<16;o<<=1){ int u=__shfl_up_sync(0x0000ffffu, sc, o); if(tid>=o) sc += u; }
                    wcnt[tid] = sc - v;
                    if(tid==15) nact_s = sc;
                }
                __syncthreads();
                int base = wcnt[wid];
                unsigned lm = (1u<<lane) - 1u;
                if(act0){ int idx = base + __popc(m0 & lm); if(idx<64){ pl[idx]=p0; wl[idx]=a0; } }
                if(act1){ int idx = base + __popc(m0) + __popc(m1 & lm); if(idx<64){ pl[idx]=p1; wl[idx]=a1; } }
                __syncthreads();

                {
                    int j = tid & 255, part = tid >> 8;
                    float s = 0.f;
                    int n = nact_s < 64 ? nact_s : 64;
                    for(int i=part; i<n; i+=2)
                        s = fmaf(wl[i], d_cnnW[((size_t)(b*PP + pl[i]))*HID + j], s);
                    sacc[part][j] = s;
                }
                __syncthreads();
                if(tid < HID){
                    float v = sacc[0][tid] + sacc[1][tid]
                            + d_stall[(size_t)(t2*BB+b)*HID + tid];
                    os[tid] = fmaxf(v, d_locw[b*HID + tid]);
                }
                __syncthreads();
                {
                    int j2 = tid & 127, p4 = tid >> 7;
                    float pr = 0.f;
                    if(j2 < VOC){
#pragma unroll 4
                        for(int c=p4*64; c<p4*64+64; c++)
                            pr = fmaf(d_WoutT[c*VOC + j2], os[c], pr);
                    }
                    pp4[p4][j2] = pr;
                }
                __syncthreads();
                if(tid < VOC){
                    out_probs[((size_t)(b*TT + t2))*VOC + tid] =
                        bout[tid] + pp4[0][tid] + pp4[1][tid] + pp4[2][tid] + pp4[3][tid];
                }
            }
        }

        // ---- single per-b barrier (17 E/P blocks) ----
        if(p < TT){
            __syncthreads();
            bt += 17;
            if(tid==0){
                __threadfence();
                atomicAdd(&d_bcnt[b*32], 1u);
                while(*(volatile unsigned*)&d_bcnt[b*32] < bt) __nanosleep(16);
                __threadfence();
            }
            __syncthreads();
        }
    }
}

// ---------------- launch ----------------
extern "C" void kernel_launch(void* const* d_in, const int* in_sizes, int n_in,
                              void* d_out, int out_size){
    const float* cnn     = (const float*)d_in[0];
    const int*   labels  = (const int*)  d_in[1];
    const float* locp    = (const float*)d_in[2];
    const float* imask   = (const float*)d_in[3];
    const float* W_init  = (const float*)d_in[5];
    const float* b_init  = (const float*)d_in[6];
    const float* emb     = (const float*)d_in[7];
    const float* W_ih    = (const float*)d_in[8];
    const float* b_ih    = (const float*)d_in[9];
    const float* W_hh    = (const float*)d_in[10];
    const float* b_hh    = (const float*)d_in[11];
    const float* W_hq    = (const float*)d_in[12];
    const float* b_hq    = (const float*)d_in[13];
    const float* K_cov   = (const float*)d_in[14];
    const float* W_att   = (const float*)d_in[15];
    const float* W_ac    = (const float*)d_in[16];
    const float* b_ac    = (const float*)d_in[17];
    const float* K_enc   = (const float*)d_in[18];
    const float* b_enc   = (const float*)d_in[19];
    const float* W_state = (const float*)d_in[20];
    const float* b_state = (const float*)d_in[21];
    const float* W_embw  = (const float*)d_in[22];
    const float* b_embw  = (const float*)d_in[23];
    const float* W_ctx   = (const float*)d_in[24];
    const float* b_ctx   = (const float*)d_in[25];
    const float* W_out   = (const float*)d_in[26];
    const float* b_out   = (const float*)d_in[27];
    const float* W_loc   = (const float*)d_in[28];
    const float* b_loc   = (const float*)d_in[29];

    float* out_probs  = (float*)d_out;
    float* out_alphas = (float*)d_out + (size_t)BB*TT*VOC;

    k_preA<<<PA_TOT, 256>>>(imask, K_cov, labels, emb, W_hh, W_hq, W_state, W_out, cnn);
    k_preB<<<PB_TOT, 256>>>(cnn, K_enc, b_enc, W_ctx, W_ih, b_ih, W_embw, b_embw, W_att);
    k_preC<<<512, 256>>>(W_init, b_init, W_loc, b_loc, locp);
    k_loop<<<BB*18, 512>>>(W_ac, b_ac, b_out, b_hh, b_hq, b_state, b_ctx,
                           out_probs, out_alphas);
}